// round 14
// baseline (speedup 1.0000x reference)
#include <cuda_runtime.h>
#include <math.h>
#include <stdint.h>

// Problem constants
#define S_LEN   256
#define B_SZ    64
#define E_DIM   300
#define H2_DIM  256
#define H_DIM   512
#define T_TAGS  10
#define START_TAG 8
#define STOP_TAG  9
#define NTOK    (S_LEN * B_SZ)     // 16384
#define G4      (4 * H2_DIM)       // 1024

#define LSTM_BLOCKS 128            // bh(2) x hq(64); each block runs BOTH dirs

typedef unsigned long long ull;

// ---------- packed f32x2 helpers (exact fp32, 2x FMA-pipe throughput) ------
__device__ __forceinline__ ull pk2(float x, float y) {
    ull r;
    asm("mov.b64 %0, {%1, %2};" : "=l"(r) : "f"(x), "f"(y));
    return r;
}
__device__ __forceinline__ void fma2(ull& c, ull a, ull b) {
    asm("fma.rn.f32x2 %0, %1, %2, %0;" : "+l"(c) : "l"(a), "l"(b));
}
__device__ __forceinline__ float2 up2(ull v) {
    float2 r;
    asm("mov.b64 {%0, %1}, %2;" : "=f"(r.x), "=f"(r.y) : "l"(v));
    return r;
}

// ---------------- scratch (device globals; no allocation allowed) ----------
__device__ __align__(16) float d_G[2][NTOK][G4];        // gate preactivations (x part + biases)
__device__ __align__(16) float d_Hout[NTOK][H_DIM];     // concatenated hidden states (S*B, 512)
__device__ __align__(16) float d_feats[NTOK][T_TAGS];   // emission scores
__device__ __align__(16) float d_hstate[2][2][B_SZ][H2_DIM]; // [parity][dir][b][h]
// Barrier flags: 4 groups (dir x bh) x 64 blocks; monotonic step values.
// Plain release-stores (no RMW serialization); reset by viterbi each call.
__device__ __align__(256) unsigned int d_flag[4][64];

__device__ __forceinline__ void st_release(unsigned int* p, unsigned int v) {
    asm volatile("st.release.gpu.global.u32 [%0], %1;" :: "l"(p), "r"(v) : "memory");
}
__device__ __forceinline__ unsigned int ld_acquire(const unsigned int* p) {
    unsigned int v;
    asm volatile("ld.acquire.gpu.global.u32 %0, [%1];" : "=r"(v) : "l"(p) : "memory");
    return v;
}
__device__ __forceinline__ void named_bar(int id, int cnt) {
    asm volatile("bar.sync %0, %1;" :: "r"(id), "r"(cnt) : "memory");
}

// ---------------- input GEMM: G = gather(emb, tok) @ wih^T + bih + bhh -----
// M=16384 (64-tile), N=1024 (64-tile), K=300 (12-tile, 25 iters exact)
// Block (0,0,0) additionally seeds d_hstate[0] from h0.
__global__ __launch_bounds__(256) void input_gemm_kernel(
    const int*   __restrict__ sent,
    const float* __restrict__ emb,
    const float* __restrict__ wih_f, const float* __restrict__ bih_f, const float* __restrict__ bhh_f,
    const float* __restrict__ wih_b, const float* __restrict__ bih_b, const float* __restrict__ bhh_b,
    const float* __restrict__ h0)
{
    const int dir = blockIdx.z;
    const float* wih = dir ? wih_b : wih_f;
    const float* bih = dir ? bih_b : bih_f;
    const float* bhh = dir ? bhh_b : bhh_f;
    float* Gout = &d_G[dir][0][0];

    __shared__ __align__(16) float As[12][64];
    __shared__ __align__(16) float Bs[12][64];
    __shared__ int toks[64];

    const int tid = threadIdx.x;
    const int n0 = blockIdx.x * 64;
    const int j0 = blockIdx.y * 64;

    if (blockIdx.x == 0 && blockIdx.y == 0 && blockIdx.z == 0) {
        float* dst = &d_hstate[0][0][0][0];
        for (int i = tid; i < 2 * B_SZ * H2_DIM; i += 256)
            dst[i] = h0[i];
    }

    if (tid < 64) toks[tid] = sent[n0 + tid];
    __syncthreads();

    const int tx = tid & 15;        // j quad
    const int ty = tid >> 4;        // n quad
    ull acc[4][2];
#pragma unroll
    for (int i = 0; i < 4; ++i) { acc[i][0] = 0ull; acc[i][1] = 0ull; }

    for (int k0 = 0; k0 < E_DIM; k0 += 12) {
#pragma unroll
        for (int i = 0; i < 3; ++i) {
            int idx = i * 256 + tid;            // 0..767 = 64 rows * 12 k
            int nn = idx / 12, kk = idx % 12;
            As[kk][nn] = emb[(size_t)toks[nn] * E_DIM + k0 + kk];
            Bs[kk][nn] = wih[(size_t)(j0 + nn) * E_DIM + k0 + kk];
        }
        __syncthreads();
#pragma unroll
        for (int kk = 0; kk < 12; ++kk) {
            float4 a = *(const float4*)&As[kk][ty * 4];
            ulonglong2 bv = *(const ulonglong2*)&Bs[kk][tx * 4];
            ull pa0 = pk2(a.x, a.x);
            ull pa1 = pk2(a.y, a.y);
            ull pa2 = pk2(a.z, a.z);
            ull pa3 = pk2(a.w, a.w);
            fma2(acc[0][0], pa0, bv.x); fma2(acc[0][1], pa0, bv.y);
            fma2(acc[1][0], pa1, bv.x); fma2(acc[1][1], pa1, bv.y);
            fma2(acc[2][0], pa2, bv.x); fma2(acc[2][1], pa2, bv.y);
            fma2(acc[3][0], pa3, bv.x); fma2(acc[3][1], pa3, bv.y);
        }
        __syncthreads();
    }

    float4 bi = *(const float4*)&bih[j0 + tx * 4];
    float4 bh = *(const float4*)&bhh[j0 + tx * 4];
    float bs0 = bi.x + bh.x, bs1 = bi.y + bh.y, bs2 = bi.z + bh.z, bs3 = bi.w + bh.w;
#pragma unroll
    for (int ii = 0; ii < 4; ++ii) {
        int n = n0 + ty * 4 + ii;
        float2 lo = up2(acc[ii][0]);
        float2 hi = up2(acc[ii][1]);
        float4 o = make_float4(lo.x + bs0, lo.y + bs1, hi.x + bs2, hi.y + bs3);
        *(float4*)&Gout[(size_t)n * G4 + j0 + tx * 4] = o;
    }
}

// ---------------- persistent bidirectional LSTM (dual-dir blocks) ----------
// 128 blocks (bh x hq) x 256 threads. Threads 0-127: forward dir; 128-255:
// backward dir. Each half owns 16 gate rows (4 hidden units, hq) x 32 batches
// (bh). Halves sync ONLY via named barriers (ids 1/2) and independent
// inter-block flag barriers, so one dir's barrier/L2 wait is hidden by the
// other dir's compute on the same SMSPs (warps land 2/SMSP, one per dir).
__global__ __launch_bounds__(256, 1) void lstm_kernel(
    const float* __restrict__ whh_f,
    const float* __restrict__ whh_b,
    const float* __restrict__ c0)
{
    const int bh = blockIdx.x >> 6;       // batch half
    const int hq = blockIdx.x & 63;       // hidden quad (4 h-units -> 16 gate rows/dir)
    const int bbase = bh * 32;
    const int tid = threadIdx.x;
    const int dir = tid >> 7;             // 0 fwd / 1 bwd
    const int ht  = tid & 127;            // thread id within dir half
    const int barid = dir + 1;            // named barrier id per dir
    unsigned int* flags = &d_flag[dir * 2 + bh][0];

    // Ws4[d][k2][rp] = (w_e[r0], w_e[r1], w_o[r0], w_o[r1]) for rowpair rp
    __shared__ __align__(16) float4 Ws4[2][128][8];   // 32 KB
    // Hsv[d][k2][bp] = (h_e[2bp], h_e[2bp+1], h_o[2bp], h_o[2bp+1])
    __shared__ __align__(16) float4 Hsv[2][32][16];   // 16 KB (one 64-k chunk/dir)
    // Gate exchange aliases this dir's Hsv (first 2 KB): Gsm[b][r], r=g*4+j
    float* gbase = (float*)&Hsv[dir][0][0];

    const float* whh = dir ? whh_b : whh_f;
    const float* Gin = &d_G[dir][0][0];

    // Load Whh slices for both dirs (full block cooperates)
    for (int i = tid; i < 2 * 128 * 8; i += 256) {
        int d = i >> 10, rem = i & 1023;
        int k2 = rem >> 3, rp = rem & 7;
        int r0 = 2 * rp;
        int rg0 = (r0 >> 2) * H2_DIM + hq * 4 + (r0 & 3);
        int rg1 = rg0 + 1;
        const float* w = d ? whh_b : whh_f;
        Ws4[d][k2][rp] = make_float4(w[(size_t)rg0 * H2_DIM + 2 * k2],
                                     w[(size_t)rg1 * H2_DIM + 2 * k2],
                                     w[(size_t)rg0 * H2_DIM + 2 * k2 + 1],
                                     w[(size_t)rg1 * H2_DIM + 2 * k2 + 1]);
    }

    // GEMM ownership: rowpair tx (rows 2tx,2tx+1 of 16) x batches (2ty,2ty+1)
    const int tx = ht & 7, ty = ht >> 3;              // ty 0..15
    const int r0 = 2 * tx;
    const int rg0 = (r0 >> 2) * H2_DIM + hq * 4 + (r0 & 3);   // rg1 = rg0+1
    const int b0 = 2 * ty;

    // staging ownership: batch stg_b (0..31), k-quarter kb
    const int stg_b = ht & 31;
    const int kb = (ht >> 5) * 16;        // 16 k values per thread per chunk
    const int stg_bp = stg_b >> 1;
    const int stg_c  = stg_b & 1;

    // pointwise ownership: 1 (b,h) pair per thread
    const int bq = ht >> 2, hh = ht & 3;
    const int hidx = hq * 4 + hh;
    float cst = c0[dir * B_SZ * H2_DIM + (bbase + bq) * H2_DIM + hidx];

    // G loads for step 0
    float2 gv0, gv1;
    {
        const int s0 = dir ? (S_LEN - 1) : 0;
        gv0 = *(const float2*)&Gin[(size_t)(s0 * B_SZ + bbase + b0) * G4 + rg0];
        gv1 = *(const float2*)&Gin[(size_t)(s0 * B_SZ + bbase + b0 + 1) * G4 + rg0];
    }

    __syncthreads();   // one-time full-block sync after Ws load

    for (int it = 0; it < S_LEN; ++it) {
        const int s = dir ? (S_LEN - 1 - it) : it;
        const int p = it & 1;
        const float* hprev = &d_hstate[p][dir][0][0];
        float* hnext = &d_hstate[p ^ 1][dir][0][0];
        const float* hp = &hprev[(bbase + stg_b) * H2_DIM];

        // prefetch chunk 0 of hprev (16 consecutive k values for one batch)
        float4 pf0 = __ldcg((const float4*)&hp[kb]);
        float4 pf1 = __ldcg((const float4*)&hp[kb + 4]);
        float4 pf2 = __ldcg((const float4*)&hp[kb + 8]);
        float4 pf3 = __ldcg((const float4*)&hp[kb + 12]);

        ull a00 = 0ull, a01 = 0ull;   // (g[r0],g[r1]) packed, batches b0 / b0+1

#pragma unroll 1
        for (int c = 0; c < 4; ++c) {
            // store prefetched chunk c into Hsv[dir] (k-pair interleaved)
            {
                int k2w = kb >> 1;
                float* t;
                t = &Hsv[dir][k2w + 0][stg_bp].x; t[stg_c] = pf0.x; t[2 + stg_c] = pf0.y;
                t = &Hsv[dir][k2w + 1][stg_bp].x; t[stg_c] = pf0.z; t[2 + stg_c] = pf0.w;
                t = &Hsv[dir][k2w + 2][stg_bp].x; t[stg_c] = pf1.x; t[2 + stg_c] = pf1.y;
                t = &Hsv[dir][k2w + 3][stg_bp].x; t[stg_c] = pf1.z; t[2 + stg_c] = pf1.w;
                t = &Hsv[dir][k2w + 4][stg_bp].x; t[stg_c] = pf2.x; t[2 + stg_c] = pf2.y;
                t = &Hsv[dir][k2w + 5][stg_bp].x; t[stg_c] = pf2.z; t[2 + stg_c] = pf2.w;
                t = &Hsv[dir][k2w + 6][stg_bp].x; t[stg_c] = pf3.x; t[2 + stg_c] = pf3.y;
                t = &Hsv[dir][k2w + 7][stg_bp].x; t[stg_c] = pf3.z; t[2 + stg_c] = pf3.w;
            }
            // prefetch chunk c+1 (hidden behind compute)
            if (c < 3) {
                const float* hpc = &hp[(c + 1) * 64 + kb];
                pf0 = __ldcg((const float4*)&hpc[0]);
                pf1 = __ldcg((const float4*)&hpc[4]);
                pf2 = __ldcg((const float4*)&hpc[8]);
                pf3 = __ldcg((const float4*)&hpc[12]);
            }
            named_bar(barid, 128);

#pragma unroll 8
            for (int k2l = 0; k2l < 32; ++k2l) {
                ulonglong2 ws = *(const ulonglong2*)&Ws4[dir][c * 32 + k2l][tx];
                float4 hv = Hsv[dir][k2l][ty];
                fma2(a00, ws.x, pk2(hv.x, hv.x));
                fma2(a01, ws.x, pk2(hv.y, hv.y));
                fma2(a00, ws.y, pk2(hv.z, hv.z));
                fma2(a01, ws.y, pk2(hv.w, hv.w));
            }
            named_bar(barid, 128);
        }

        // write gates into exchange buffer (aliases Hsv[dir]; safe after bar)
        {
            float2 u0 = up2(a00), u1 = up2(a01);
            gbase[(b0) * 16 + r0]         = u0.x + gv0.x;
            gbase[(b0) * 16 + r0 + 1]     = u0.y + gv0.y;
            gbase[(b0 + 1) * 16 + r0]     = u1.x + gv1.x;
            gbase[(b0 + 1) * 16 + r0 + 1] = u1.y + gv1.y;
        }
        named_bar(barid, 128);

        // pointwise: one (b,h) pair per thread (local rows r = g*4 + hh)
        {
            float gi = gbase[bq * 16 + hh];
            float gf = gbase[bq * 16 + 4 + hh];
            float gg = gbase[bq * 16 + 8 + hh];
            float go = gbase[bq * 16 + 12 + hh];
            float si = 1.f / (1.f + expf(-gi));
            float sf = 1.f / (1.f + expf(-gf));
            float so = 1.f / (1.f + expf(-go));
            cst = sf * cst + si * tanhf(gg);
            float h = so * tanhf(cst);
            __stcg(&hnext[(bbase + bq) * H2_DIM + hidx], h);
            d_Hout[s * B_SZ + bbase + bq][dir * H2_DIM + hidx] = h;
        }

        if (it < S_LEN - 1) {
            // prefetch next step's G BEFORE the inter-block wait
            const int sn = dir ? (S_LEN - 2 - it) : (it + 1);
            float2 gn0 = *(const float2*)&Gin[(size_t)(sn * B_SZ + bbase + b0) * G4 + rg0];
            float2 gn1 = *(const float2*)&Gin[(size_t)(sn * B_SZ + bbase + b0 + 1) * G4 + rg0];

            // inter-block group barrier: release-store own flag, poll 64 flags
            named_bar(barid, 128);              // all h stores of this half done
            if (ht == 0) st_release(&flags[hq], (unsigned int)(it + 1));
            if (ht < 64) {
                const unsigned int target = (unsigned int)(it + 1);
                while (ld_acquire(&flags[ht]) < target) { }
            }
            named_bar(barid, 128);

            gv0 = gn0; gv1 = gn1;
        }
    }
}

// ---------------- feats: (16384 x 512) @ (512 x 10) + b ---------------------
__global__ __launch_bounds__(256) void feats_kernel(
    const float* __restrict__ W_out, const float* __restrict__ b_out)
{
    const int warp = threadIdx.x >> 5;
    const int lane = threadIdx.x & 31;
    const int n = blockIdx.x * 8 + warp;
    const float4* h4 = (const float4*)&d_Hout[n][0];

    float acc[T_TAGS];
#pragma unroll
    for (int t = 0; t < T_TAGS; ++t) acc[t] = 0.f;

#pragma unroll
    for (int i = 0; i < 4; ++i) {
        int q = i * 32 + lane;               // float4 index (0..127)
        float4 hv = h4[q];
#pragma unroll
        for (int t = 0; t < T_TAGS; ++t) {
            float4 w = *(const float4*)&W_out[t * H_DIM + q * 4];
            acc[t] += hv.x * w.x + hv.y * w.y + hv.z * w.z + hv.w * w.w;
        }
    }
#pragma unroll
    for (int t = 0; t < T_TAGS; ++t) {
        float v = acc[t];
#pragma unroll
        for (int off = 16; off > 0; off >>= 1)
            v += __shfl_down_sync(0xffffffffu, v, off);
        if (lane == 0) d_feats[n][t] = v + b_out[t];
    }
}

// ---------------- Viterbi: one warp per batch --------------------------------
// smem broadcast of fv replaces the 10-deep serial SHFL chain (26 cyc each).
// Also resets the lstm barrier flags for the next graph replay.
__global__ void viterbi_kernel(const float* __restrict__ trans, float* __restrict__ out) {
    const int b = blockIdx.x;
    const int lane = threadIdx.x;
    __shared__ float tr[T_TAGS][T_TAGS];
    __shared__ float fvs[16];
    __shared__ unsigned char bp[S_LEN][T_TAGS];

    if (b == 0) {
        d_flag[0][lane] = 0u; d_flag[0][32 + lane] = 0u;
        d_flag[1][lane] = 0u; d_flag[1][32 + lane] = 0u;
        d_flag[2][lane] = 0u; d_flag[2][32 + lane] = 0u;
        d_flag[3][lane] = 0u; d_flag[3][32 + lane] = 0u;
    }

    for (int i = lane; i < T_TAGS * T_TAGS; i += 32)
        tr[i / T_TAGS][i % T_TAGS] = trans[i];
    __syncwarp();

    const int ln = lane < T_TAGS ? lane : 0;   // safe index for lanes >= 10
    float fv = (lane == START_TAG) ? 0.f : -10000.f;
    float fcur = d_feats[b * S_LEN][ln];

    for (int s = 0; s < S_LEN; ++s) {
        float fnxt = (s + 1 < S_LEN) ? d_feats[b * S_LEN + s + 1][ln] : 0.f;
        if (lane < T_TAGS) fvs[lane] = fv;
        __syncwarp();
        float best = -3.4e38f;
        int arg = 0;
#pragma unroll
        for (int pv = 0; pv < T_TAGS; ++pv) {
            float v = fvs[pv] + tr[ln][pv];
            if (v > best) { best = v; arg = pv; }   // strict > keeps FIRST max
        }
        if (lane < T_TAGS) bp[s][lane] = (unsigned char)arg;
        fv = best + fcur;
        fcur = fnxt;
        __syncwarp();
    }

    float term = fv + tr[STOP_TAG][ln];
    if (lane < T_TAGS) fvs[lane] = term;
    __syncwarp();

    if (lane == 0) {
        float bestv = -3.4e38f;
        int bestt = 0;
#pragma unroll
        for (int t = 0; t < T_TAGS; ++t) {
            float v = fvs[t];
            if (v > bestv) { bestv = v; bestt = t; }
        }
        out[b] = bestv;                      // path_score (B,1)
        float* pathout = out + B_SZ + b * S_LEN;
        int cur = bestt;
        pathout[S_LEN - 1] = (float)cur;
        for (int s = S_LEN - 2; s >= 0; --s) {
            cur = bp[s + 1][cur];
            pathout[s] = (float)cur;
        }
    }
}

// ---------------- launch ------------------------------------------------------
extern "C" void kernel_launch(void* const* d_in, const int* in_sizes, int n_in,
                              void* d_out, int out_size) {
    const int*   sent  = (const int*)  d_in[0];
    const float* emb   = (const float*)d_in[1];
    const float* wih_f = (const float*)d_in[2];
    const float* whh_f = (const float*)d_in[3];
    const float* bih_f = (const float*)d_in[4];
    const float* bhh_f = (const float*)d_in[5];
    const float* wih_b = (const float*)d_in[6];
    const float* whh_b = (const float*)d_in[7];
    const float* bih_b = (const float*)d_in[8];
    const float* bhh_b = (const float*)d_in[9];
    const float* W_out = (const float*)d_in[10];
    const float* b_out = (const float*)d_in[11];

    // Resolve trailing-argument order at runtime (transitions = 100 elems).
    const float *trans, *h0, *c0;
    if (n_in >= 15 && in_sizes[12] == 100) {
        trans = (const float*)d_in[12];
        h0    = (const float*)d_in[13];
        c0    = (const float*)d_in[14];
    } else {
        h0    = (const float*)d_in[12];
        c0    = (const float*)d_in[13];
        trans = (const float*)d_in[14];
    }

    float* out = (float*)d_out;

    dim3 g(NTOK / 64, G4 / 64, 2);   // 256 x 16 x 2
    input_gemm_kernel<<<g, 256>>>(sent, emb, wih_f, bih_f, bhh_f,
                                  wih_b, bih_b, bhh_b, h0);
    lstm_kernel<<<LSTM_BLOCKS, 256>>>(whh_f, whh_b, c0);
    feats_kernel<<<NTOK / 8, 256>>>(W_out, b_out);
    viterbi_kernel<<<B_SZ, 32>>>(trans, out);
    (void)out_size; (void)n_in;
}

// round 15
// speedup vs baseline: 1.5000x; 1.5000x over previous
#include <cuda_runtime.h>
#include <math.h>
#include <stdint.h>

// Problem constants
#define S_LEN   256
#define B_SZ    64
#define E_DIM   300
#define H2_DIM  256
#define H_DIM   512
#define T_TAGS  10
#define START_TAG 8
#define STOP_TAG  9
#define NTOK    (S_LEN * B_SZ)     // 16384
#define G4      (4 * H2_DIM)       // 1024

#define LSTM_BLOCKS 256            // dir(2) x bh(2) x hseg(64); 2 blocks/SM

typedef unsigned long long ull;

// ---------- packed f32x2 helpers (exact fp32, 2x FMA-pipe throughput) ------
__device__ __forceinline__ ull pk2(float x, float y) {
    ull r;
    asm("mov.b64 %0, {%1, %2};" : "=l"(r) : "f"(x), "f"(y));
    return r;
}
__device__ __forceinline__ void fma2(ull& c, ull a, ull b) {
    asm("fma.rn.f32x2 %0, %1, %2, %0;" : "+l"(c) : "l"(a), "l"(b));
}
__device__ __forceinline__ float2 up2(ull v) {
    float2 r;
    asm("mov.b64 {%0, %1}, %2;" : "=f"(r.x), "=f"(r.y) : "l"(v));
    return r;
}

// ---------------- scratch (device globals; no allocation allowed) ----------
__device__ __align__(16) float d_G[2][NTOK][G4];        // gate preactivations (x part + biases)
__device__ __align__(16) float d_Hout[NTOK][H_DIM];     // concatenated hidden states (S*B, 512)
__device__ __align__(16) float d_feats[NTOK][T_TAGS];   // emission scores
__device__ __align__(16) float d_hstate[2][2][B_SZ][H2_DIM]; // [parity][dir][b][h]
// 8 monotonic barrier sub-counters (4 groups x 2 subs), each on its own 128B
// line. Zero-init .bss; reset by viterbi_kernel each call (stream-ordered
// after lstm) so graph replays stay deterministic.
__device__ __align__(256) unsigned int d_cnt[8][32];

// ---------- barrier primitives (release-red arrive, acquire poll) ----------
__device__ __forceinline__ void bar_arrive(unsigned int* c) {
    asm volatile("red.release.gpu.global.add.u32 [%0], 1;" :: "l"(c) : "memory");
}
__device__ __forceinline__ unsigned int bar_ld_acq(const unsigned int* c) {
    unsigned int v;
    asm volatile("ld.acquire.gpu.global.u32 %0, [%1];" : "=r"(v) : "l"(c) : "memory");
    return v;
}

// ---------------- input GEMM: G = gather(emb, tok) @ wih^T + bih + bhh -----
// M=16384 (64-tile), N=1024 (64-tile), K=300 (12-tile, 25 iters exact)
// Block (0,0,0) additionally seeds d_hstate[0] from h0.
__global__ __launch_bounds__(256) void input_gemm_kernel(
    const int*   __restrict__ sent,
    const float* __restrict__ emb,
    const float* __restrict__ wih_f, const float* __restrict__ bih_f, const float* __restrict__ bhh_f,
    const float* __restrict__ wih_b, const float* __restrict__ bih_b, const float* __restrict__ bhh_b,
    const float* __restrict__ h0)
{
    const int dir = blockIdx.z;
    const float* wih = dir ? wih_b : wih_f;
    const float* bih = dir ? bih_b : bih_f;
    const float* bhh = dir ? bhh_b : bhh_f;
    float* Gout = &d_G[dir][0][0];

    __shared__ __align__(16) float As[12][64];
    __shared__ __align__(16) float Bs[12][64];
    __shared__ int toks[64];

    const int tid = threadIdx.x;
    const int n0 = blockIdx.x * 64;
    const int j0 = blockIdx.y * 64;

    if (blockIdx.x == 0 && blockIdx.y == 0 && blockIdx.z == 0) {
        float* dst = &d_hstate[0][0][0][0];
        for (int i = tid; i < 2 * B_SZ * H2_DIM; i += 256)
            dst[i] = h0[i];
    }

    if (tid < 64) toks[tid] = sent[n0 + tid];
    __syncthreads();

    const int tx = tid & 15;        // j quad
    const int ty = tid >> 4;        // n quad
    ull acc[4][2];
#pragma unroll
    for (int i = 0; i < 4; ++i) { acc[i][0] = 0ull; acc[i][1] = 0ull; }

    for (int k0 = 0; k0 < E_DIM; k0 += 12) {
#pragma unroll
        for (int i = 0; i < 3; ++i) {
            int idx = i * 256 + tid;            // 0..767 = 64 rows * 12 k
            int nn = idx / 12, kk = idx % 12;
            As[kk][nn] = emb[(size_t)toks[nn] * E_DIM + k0 + kk];
            Bs[kk][nn] = wih[(size_t)(j0 + nn) * E_DIM + k0 + kk];
        }
        __syncthreads();
#pragma unroll
        for (int kk = 0; kk < 12; ++kk) {
            float4 a = *(const float4*)&As[kk][ty * 4];
            ulonglong2 bv = *(const ulonglong2*)&Bs[kk][tx * 4];
            ull pa0 = pk2(a.x, a.x);
            ull pa1 = pk2(a.y, a.y);
            ull pa2 = pk2(a.z, a.z);
            ull pa3 = pk2(a.w, a.w);
            fma2(acc[0][0], pa0, bv.x); fma2(acc[0][1], pa0, bv.y);
            fma2(acc[1][0], pa1, bv.x); fma2(acc[1][1], pa1, bv.y);
            fma2(acc[2][0], pa2, bv.x); fma2(acc[2][1], pa2, bv.y);
            fma2(acc[3][0], pa3, bv.x); fma2(acc[3][1], pa3, bv.y);
        }
        __syncthreads();
    }

    float4 bi = *(const float4*)&bih[j0 + tx * 4];
    float4 bh = *(const float4*)&bhh[j0 + tx * 4];
    float bs0 = bi.x + bh.x, bs1 = bi.y + bh.y, bs2 = bi.z + bh.z, bs3 = bi.w + bh.w;
#pragma unroll
    for (int ii = 0; ii < 4; ++ii) {
        int n = n0 + ty * 4 + ii;
        float2 lo = up2(acc[ii][0]);
        float2 hi = up2(acc[ii][1]);
        float4 o = make_float4(lo.x + bs0, lo.y + bs1, hi.x + bs2, hi.y + bs3);
        *(float4*)&Gout[(size_t)n * G4 + j0 + tx * 4] = o;
    }
}

// ---------------- persistent bidirectional LSTM -----------------------------
// 256 blocks x 128 threads, 2 co-resident blocks/SM so one block's barrier
// poll overlaps the other block's compute. Block = dir x batch-half x
// hidden-quad (4 h-units -> 16 gate rows) x 32 batches. Same structure and
// barrier primitive as the proven 128-block kernel; each 64-block group
// arrives on 2 sub-counters (32 red's each) to keep arrival serialization low.
__global__ __launch_bounds__(128, 2) void lstm_kernel(
    const float* __restrict__ whh_f,
    const float* __restrict__ whh_b,
    const float* __restrict__ c0)
{
    const int dir   = blockIdx.x >> 7;
    const int rem   = blockIdx.x & 127;
    const int bh    = rem >> 6;       // batch half
    const int hseg  = rem & 63;       // hidden quad (4 units -> 16 gate rows)
    const int bbase = bh * 32;
    const int tid   = threadIdx.x;
    const int grp   = dir * 2 + bh;   // barrier group (0..3)
    unsigned int* my_cnt = &d_cnt[grp * 2 + (hseg & 1)][0];
    const unsigned int* c0p = &d_cnt[grp * 2 + 0][0];
    const unsigned int* c1p = &d_cnt[grp * 2 + 1][0];

    // Ws4[k2][rp] = (w[2k2][2rp], w[2k2][2rp+1], w[2k2+1][2rp], w[2k2+1][2rp+1])
    __shared__ __align__(16) float4 Ws4[128][8];     // 16 KB (Whh slice, 16 rows)
    // Hsv[k2][bp] = (h[2k2][2bp], h[2k2][2bp+1], h[2k2+1][2bp], h[2k2+1][2bp+1])
    __shared__ __align__(16) float4 Hsv[32][16];     // 8 KB (one 64-k chunk)
    __shared__ float Gsm[32][17];                    // gate exchange [b_local][r]

    const float* whh = dir ? whh_b : whh_f;
    const float* Gin = &d_G[dir][0][0];

    // Build Ws4 once (1024 float4 entries, 8 per thread)
    for (int i = tid; i < 128 * 8; i += 128) {
        int k2 = i >> 3, rp = i & 7;
        int r0 = 2 * rp;                                 // local row (even)
        int rg0 = (r0 >> 2) * H2_DIM + hseg * 4 + (r0 & 3);
        int rg1 = rg0 + 1;                               // u in {0,2} -> u+1 same gate
        Ws4[k2][rp] = make_float4(whh[(size_t)rg0 * H2_DIM + 2 * k2],
                                  whh[(size_t)rg1 * H2_DIM + 2 * k2],
                                  whh[(size_t)rg0 * H2_DIM + 2 * k2 + 1],
                                  whh[(size_t)rg1 * H2_DIM + 2 * k2 + 1]);
    }

    // GEMM ownership: row pair (2tx, 2tx+1 of 16) x batches (2ty, 2ty+1)
    const int tx = tid & 7, ty = tid >> 3;    // tx 0..7, ty 0..15
    const int r0 = 2 * tx;
    const int rg0 = (r0 >> 2) * H2_DIM + hseg * 4 + (r0 & 3);  // rg1 = rg0+1
    const int b0 = 2 * ty;

    // staging ownership: batch stg_b (0..31), k-quarter kb (16 k values)
    const int stg_b  = tid & 31;
    const int kbase0 = (tid >> 5) * 16;
    const int stg_bp = stg_b >> 1;
    const int stg_c  = stg_b & 1;

    // pointwise ownership: thread -> (b = tid>>2, hh = tid&3)
    const int bq = tid >> 2, hh = tid & 3;
    const int hidx = hseg * 4 + hh;
    float cst = c0[dir * B_SZ * H2_DIM + (bbase + bq) * H2_DIM + hidx];

    // G loads for step 0
    float2 gv0, gv1;
    {
        const int s0 = dir ? (S_LEN - 1) : 0;
        gv0 = *(const float2*)&Gin[(size_t)(s0 * B_SZ + bbase + b0) * G4 + rg0];
        gv1 = *(const float2*)&Gin[(size_t)(s0 * B_SZ + bbase + b0 + 1) * G4 + rg0];
    }

    __syncthreads();

    for (int it = 0; it < S_LEN; ++it) {
        const int s = dir ? (S_LEN - 1 - it) : it;
        const int p = it & 1;
        const float* hprev = &d_hstate[p][dir][0][0];
        float* hnext = &d_hstate[p ^ 1][dir][0][0];
        const float* hp = &hprev[(bbase + stg_b) * H2_DIM];

        // prefetch chunk 0 of hprev (16 consecutive k values for one batch)
        float4 pf[4];
#pragma unroll
        for (int u = 0; u < 4; ++u)
            pf[u] = __ldcg((const float4*)&hp[kbase0 + 4 * u]);

        ull a00 = 0ull, a01 = 0ull;   // (g[r0],g[r1]) packed, batches b0 / b0+1

#pragma unroll 1
        for (int c = 0; c < 4; ++c) {
            // store prefetched chunk c into Hsv (k-pair interleaved)
#pragma unroll
            for (int u = 0; u < 4; ++u) {
                int kl = kbase0 + 4 * u;          // multiple of 4
                int k2l = kl >> 1;                // even
                float* t0 = &Hsv[k2l][stg_bp].x;
                t0[stg_c] = pf[u].x; t0[2 + stg_c] = pf[u].y;
                float* t1 = &Hsv[k2l + 1][stg_bp].x;
                t1[stg_c] = pf[u].z; t1[2 + stg_c] = pf[u].w;
            }
            // prefetch chunk c+1 (hidden behind compute)
            if (c < 3) {
#pragma unroll
                for (int u = 0; u < 4; ++u)
                    pf[u] = __ldcg((const float4*)&hp[(c + 1) * 64 + kbase0 + 4 * u]);
            }
            __syncthreads();

#pragma unroll 8
            for (int k2l = 0; k2l < 32; ++k2l) {
                ulonglong2 ws = *(const ulonglong2*)&Ws4[c * 32 + k2l][tx];
                float4 hv = Hsv[k2l][ty];
                fma2(a00, ws.x, pk2(hv.x, hv.x));   // k even, batch b0
                fma2(a01, ws.x, pk2(hv.y, hv.y));   // k even, batch b1
                fma2(a00, ws.y, pk2(hv.z, hv.z));   // k odd,  batch b0
                fma2(a01, ws.y, pk2(hv.w, hv.w));   // k odd,  batch b1
            }
            __syncthreads();
        }

        // write gates to exchange buffer (+ x-part from G)
        {
            float2 u0 = up2(a00), u1 = up2(a01);
            Gsm[b0][r0]         = u0.x + gv0.x;
            Gsm[b0][r0 + 1]     = u0.y + gv0.y;
            Gsm[b0 + 1][r0]     = u1.x + gv1.x;
            Gsm[b0 + 1][r0 + 1] = u1.y + gv1.y;
        }
        __syncthreads();

        // pointwise: one (b,h) pair per thread (local rows r = g*4 + hh)
        {
            float gi = Gsm[bq][hh];
            float gf = Gsm[bq][4 + hh];
            float gg = Gsm[bq][8 + hh];
            float go = Gsm[bq][12 + hh];
            float si = 1.f / (1.f + expf(-gi));
            float sf = 1.f / (1.f + expf(-gf));
            float so = 1.f / (1.f + expf(-go));
            cst = sf * cst + si * tanhf(gg);
            float h = so * tanhf(cst);
            __stcg(&hnext[(bbase + bq) * H2_DIM + hidx], h);
            d_Hout[s * B_SZ + bbase + bq][dir * H2_DIM + hidx] = h;
        }

        if (it < S_LEN - 1) {
            // prefetch next step's G BEFORE the barrier (independent of h)
            const int sn = dir ? (S_LEN - 2 - it) : (it + 1);
            float2 gn0 = *(const float2*)&Gin[(size_t)(sn * B_SZ + bbase + b0) * G4 + rg0];
            float2 gn1 = *(const float2*)&Gin[(size_t)(sn * B_SZ + bbase + b0 + 1) * G4 + rg0];

            // group barrier: release-arrive on own sub-counter, poll both
            __syncthreads();
            if (tid == 0) {
                bar_arrive(my_cnt);
                const unsigned int target = (unsigned int)(it + 1) * 32;
                while (bar_ld_acq(c0p) < target) { }
                while (bar_ld_acq(c1p) < target) { }
            }
            __syncthreads();

            gv0 = gn0; gv1 = gn1;
        }
    }
}

// ---------------- feats: (16384 x 512) @ (512 x 10) + b ---------------------
__global__ __launch_bounds__(256) void feats_kernel(
    const float* __restrict__ W_out, const float* __restrict__ b_out)
{
    const int warp = threadIdx.x >> 5;
    const int lane = threadIdx.x & 31;
    const int n = blockIdx.x * 8 + warp;
    const float4* h4 = (const float4*)&d_Hout[n][0];

    float acc[T_TAGS];
#pragma unroll
    for (int t = 0; t < T_TAGS; ++t) acc[t] = 0.f;

#pragma unroll
    for (int i = 0; i < 4; ++i) {
        int q = i * 32 + lane;               // float4 index (0..127)
        float4 hv = h4[q];
#pragma unroll
        for (int t = 0; t < T_TAGS; ++t) {
            float4 w = *(const float4*)&W_out[t * H_DIM + q * 4];
            acc[t] += hv.x * w.x + hv.y * w.y + hv.z * w.z + hv.w * w.w;
        }
    }
#pragma unroll
    for (int t = 0; t < T_TAGS; ++t) {
        float v = acc[t];
#pragma unroll
        for (int off = 16; off > 0; off >>= 1)
            v += __shfl_down_sync(0xffffffffu, v, off);
        if (lane == 0) d_feats[n][t] = v + b_out[t];
    }
}

// ---------------- Viterbi: one warp per batch --------------------------------
// Also resets the lstm barrier counters (stream-ordered after lstm_kernel).
__global__ void viterbi_kernel(const float* __restrict__ trans, float* __restrict__ out) {
    const int b = blockIdx.x;
    const int lane = threadIdx.x;
    __shared__ float tr[T_TAGS][T_TAGS];
    __shared__ unsigned char bp[S_LEN][T_TAGS];

    if (b == 0 && lane < 8) d_cnt[lane][0] = 0u;

    for (int i = lane; i < T_TAGS * T_TAGS; i += 32)
        tr[i / T_TAGS][i % T_TAGS] = trans[i];
    __syncwarp();

    const int ln = lane < T_TAGS ? lane : 0;   // safe index for lanes >= 10
    float fv = (lane == START_TAG) ? 0.f : -10000.f;
    float fcur = d_feats[b * S_LEN][ln];

    for (int s = 0; s < S_LEN; ++s) {
        float fnxt = (s + 1 < S_LEN) ? d_feats[b * S_LEN + s + 1][ln] : 0.f;
        float best = -3.4e38f;
        int arg = 0;
#pragma unroll
        for (int pv = 0; pv < T_TAGS; ++pv) {
            float fp = __shfl_sync(0xffffffffu, fv, pv);
            float v = fp + tr[ln][pv];
            if (v > best) { best = v; arg = pv; }   // strict > keeps FIRST max
        }
        if (lane < T_TAGS) bp[s][lane] = (unsigned char)arg;
        fv = best + fcur;
        fcur = fnxt;
        __syncwarp();
    }

    float term = fv + tr[STOP_TAG][ln];
    __syncwarp();

    float bestv = -3.4e38f;
    int bestt = 0;
#pragma unroll
    for (int t = 0; t < T_TAGS; ++t) {
        float v = __shfl_sync(0xffffffffu, term, t);
        if (v > bestv) { bestv = v; bestt = t; }
    }

    if (lane == 0) {
        out[b] = bestv;                      // path_score (B,1)
        float* pathout = out + B_SZ + b * S_LEN;
        int cur = bestt;
        pathout[S_LEN - 1] = (float)cur;
        for (int s = S_LEN - 2; s >= 0; --s) {
            cur = bp[s + 1][cur];
            pathout[s] = (float)cur;
        }
    }
}

// ---------------- launch ------------------------------------------------------
extern "C" void kernel_launch(void* const* d_in, const int* in_sizes, int n_in,
                              void* d_out, int out_size) {
    const int*   sent  = (const int*)  d_in[0];
    const float* emb   = (const float*)d_in[1];
    const float* wih_f = (const float*)d_in[2];
    const float* whh_f = (const float*)d_in[3];
    const float* bih_f = (const float*)d_in[4];
    const float* bhh_f = (const float*)d_in[5];
    const float* wih_b = (const float*)d_in[6];
    const float* whh_b = (const float*)d_in[7];
    const float* bih_b = (const float*)d_in[8];
    const float* bhh_b = (const float*)d_in[9];
    const float* W_out = (const float*)d_in[10];
    const float* b_out = (const float*)d_in[11];

    // Resolve trailing-argument order at runtime (transitions = 100 elems).
    const float *trans, *h0, *c0;
    if (n_in >= 15 && in_sizes[12] == 100) {
        trans = (const float*)d_in[12];
        h0    = (const float*)d_in[13];
        c0    = (const float*)d_in[14];
    } else {
        h0    = (const float*)d_in[12];
        c0    = (const float*)d_in[13];
        trans = (const float*)d_in[14];
    }

    float* out = (float*)d_out;

    dim3 g(NTOK / 64, G4 / 64, 2);   // 256 x 16 x 2
    input_gemm_kernel<<<g, 256>>>(sent, emb, wih_f, bih_f, bhh_f,
                                  wih_b, bih_b, bhh_b, h0);
    lstm_kernel<<<LSTM_BLOCKS, 128>>>(whh_f, whh_b, c0);
    feats_kernel<<<NTOK / 8, 256>>>(W_out, b_out);
    viterbi_kernel<<<B_SZ, 32>>>(trans, out);
    (void)out_size; (void)n_in;
}

// round 16
// speedup vs baseline: 1.7111x; 1.1407x over previous
#include <cuda_runtime.h>
#include <math.h>
#include <stdint.h>

// Problem constants
#define S_LEN   256
#define B_SZ    64
#define E_DIM   300
#define H2_DIM  256
#define H_DIM   512
#define T_TAGS  10
#define START_TAG 8
#define STOP_TAG  9
#define NTOK    (S_LEN * B_SZ)     // 16384
#define G4      (4 * H2_DIM)       // 1024

#define LSTM_BLOCKS 128

typedef unsigned long long ull;

// ---------- packed f32x2 helpers (exact fp32, 2x FMA-pipe throughput) ------
__device__ __forceinline__ ull pk2(float x, float y) {
    ull r;
    asm("mov.b64 %0, {%1, %2};" : "=l"(r) : "f"(x), "f"(y));
    return r;
}
__device__ __forceinline__ void fma2(ull& c, ull a, ull b) {
    asm("fma.rn.f32x2 %0, %1, %2, %0;" : "+l"(c) : "l"(a), "l"(b));
}
__device__ __forceinline__ float2 up2(ull v) {
    float2 r;
    asm("mov.b64 {%0, %1}, %2;" : "=f"(r.x), "=f"(r.y) : "l"(v));
    return r;
}

// ---------------- scratch (device globals; no allocation allowed) ----------
__device__ __align__(16) float d_G[2][NTOK][G4];        // gate preactivations (x part + biases)
__device__ __align__(16) float d_Hout[NTOK][H_DIM];     // concatenated hidden states (S*B, 512)
__device__ __align__(16) float d_feats[NTOK][T_TAGS];   // emission scores
__device__ __align__(16) float d_hstate[2][2][B_SZ][H2_DIM]; // [parity][dir][b][h]
// 16 monotonic barrier sub-counters (4 groups x 4 subs), each on its own 128B
// line. Zero-init .bss; reset by viterbi_kernel (stream-ordered after lstm)
// so graph replays stay deterministic.
__device__ __align__(256) unsigned int d_cnt[16][32];

// ---------- barrier primitives (release-red arrive, acquire poll) ----------
__device__ __forceinline__ void bar_arrive(unsigned int* c) {
    asm volatile("red.release.gpu.global.add.u32 [%0], 1;" :: "l"(c) : "memory");
}
__device__ __forceinline__ unsigned int bar_ld_acq(const unsigned int* c) {
    unsigned int v;
    asm volatile("ld.acquire.gpu.global.u32 %0, [%1];" : "=r"(v) : "l"(c) : "memory");
    return v;
}

// ---------------- no-op kernels (position lstm as the 4th launch for ncu) --
__global__ void noop_kernel() {}

// ---------------- input GEMM: G = gather(emb, tok) @ wih^T + bih + bhh -----
// M=16384 (64-tile), N=1024 (64-tile), K=300 (12-tile, 25 iters exact)
// Block (0,0,0) additionally seeds d_hstate[0] from h0.
__global__ __launch_bounds__(256) void input_gemm_kernel(
    const int*   __restrict__ sent,
    const float* __restrict__ emb,
    const float* __restrict__ wih_f, const float* __restrict__ bih_f, const float* __restrict__ bhh_f,
    const float* __restrict__ wih_b, const float* __restrict__ bih_b, const float* __restrict__ bhh_b,
    const float* __restrict__ h0)
{
    const int dir = blockIdx.z;
    const float* wih = dir ? wih_b : wih_f;
    const float* bih = dir ? bih_b : bih_f;
    const float* bhh = dir ? bhh_b : bhh_f;
    float* Gout = &d_G[dir][0][0];

    __shared__ __align__(16) float As[12][64];
    __shared__ __align__(16) float Bs[12][64];
    __shared__ int toks[64];

    const int tid = threadIdx.x;
    const int n0 = blockIdx.x * 64;
    const int j0 = blockIdx.y * 64;

    if (blockIdx.x == 0 && blockIdx.y == 0 && blockIdx.z == 0) {
        float* dst = &d_hstate[0][0][0][0];
        for (int i = tid; i < 2 * B_SZ * H2_DIM; i += 256)
            dst[i] = h0[i];
    }

    if (tid < 64) toks[tid] = sent[n0 + tid];
    __syncthreads();

    const int tx = tid & 15;        // j quad
    const int ty = tid >> 4;        // n quad
    ull acc[4][2];
#pragma unroll
    for (int i = 0; i < 4; ++i) { acc[i][0] = 0ull; acc[i][1] = 0ull; }

    for (int k0 = 0; k0 < E_DIM; k0 += 12) {
#pragma unroll
        for (int i = 0; i < 3; ++i) {
            int idx = i * 256 + tid;            // 0..767 = 64 rows * 12 k
            int nn = idx / 12, kk = idx % 12;
            As[kk][nn] = emb[(size_t)toks[nn] * E_DIM + k0 + kk];
            Bs[kk][nn] = wih[(size_t)(j0 + nn) * E_DIM + k0 + kk];
        }
        __syncthreads();
#pragma unroll
        for (int kk = 0; kk < 12; ++kk) {
            float4 a = *(const float4*)&As[kk][ty * 4];
            ulonglong2 bv = *(const ulonglong2*)&Bs[kk][tx * 4];
            ull pa0 = pk2(a.x, a.x);
            ull pa1 = pk2(a.y, a.y);
            ull pa2 = pk2(a.z, a.z);
            ull pa3 = pk2(a.w, a.w);
            fma2(acc[0][0], pa0, bv.x); fma2(acc[0][1], pa0, bv.y);
            fma2(acc[1][0], pa1, bv.x); fma2(acc[1][1], pa1, bv.y);
            fma2(acc[2][0], pa2, bv.x); fma2(acc[2][1], pa2, bv.y);
            fma2(acc[3][0], pa3, bv.x); fma2(acc[3][1], pa3, bv.y);
        }
        __syncthreads();
    }

    float4 bi = *(const float4*)&bih[j0 + tx * 4];
    float4 bh = *(const float4*)&bhh[j0 + tx * 4];
    float bs0 = bi.x + bh.x, bs1 = bi.y + bh.y, bs2 = bi.z + bh.z, bs3 = bi.w + bh.w;
#pragma unroll
    for (int ii = 0; ii < 4; ++ii) {
        int n = n0 + ty * 4 + ii;
        float2 lo = up2(acc[ii][0]);
        float2 hi = up2(acc[ii][1]);
        float4 o = make_float4(lo.x + bs0, lo.y + bs1, hi.x + bs2, hi.y + bs3);
        *(float4*)&Gout[(size_t)n * G4 + j0 + tx * 4] = o;
    }
}

// ---------------- persistent bidirectional LSTM -----------------------------
// 128 blocks x 128 threads (R10 structure): dir = bid>>6; slice -> batch half
// (32 b) x hidden seg (8 h-units = 32 gate rows). Changes vs R10:
//  - 2 chunks of 128 k (was 4x64): 7 syncs/step (was 11), MLP=8 prefetch
//  - barrier arrivals split over 4 sub-counters per group (8 RMWs each)
//  - gate exchange aliases Hsv (smem = 48KB exactly)
__global__ __launch_bounds__(128, 1) void lstm_kernel(
    const float* __restrict__ whh_f,
    const float* __restrict__ whh_b,
    const float* __restrict__ c0)
{
    const int dir   = blockIdx.x >> 6;
    const int slice = blockIdx.x & 63;
    const int bh    = slice >> 5;     // 0/1 batch half
    const int hseg  = slice & 31;     // hidden segment (8 units -> 32 gate rows)
    const int bbase = bh * 32;
    const int tid   = threadIdx.x;
    const int grp   = dir * 2 + bh;   // barrier group (0..3)
    unsigned int* my_cnt = &d_cnt[grp * 4 + (hseg & 3)][0];
    const unsigned int* cbase = &d_cnt[grp * 4][0];

    // Ws4[k2][rp] = (w[2k2][2rp], w[2k2][2rp+1], w[2k2+1][2rp], w[2k2+1][2rp+1])
    __shared__ __align__(16) float4 Ws4[128][16];   // 32 KB (whole Whh slice)
    // Hsv[k2][bp] = (h[2k2][2bp], h[2k2][2bp+1], h[2k2+1][2bp], h[2k2+1][2bp+1])
    __shared__ __align__(16) float4 Hsv[64][16];    // 16 KB (one 128-k chunk)
    float (*Gsm)[33] = (float(*)[33])&Hsv[0][0];    // aliased gate exchange (4.2KB)

    const float* whh = dir ? whh_b : whh_f;
    const float* Gin = &d_G[dir][0][0];

    // Build Ws4 once (2048 float4 entries, 16 per thread)
    for (int i = tid; i < 128 * 16; i += 128) {
        int k2 = i >> 4, rp = i & 15;
        int r0 = 2 * rp, r1 = r0 + 1;
        int rg0 = (r0 >> 3) * H2_DIM + hseg * 8 + (r0 & 7);
        int rg1 = (r1 >> 3) * H2_DIM + hseg * 8 + (r1 & 7);
        Ws4[k2][rp] = make_float4(whh[(size_t)rg0 * H2_DIM + 2 * k2],
                                  whh[(size_t)rg1 * H2_DIM + 2 * k2],
                                  whh[(size_t)rg0 * H2_DIM + 2 * k2 + 1],
                                  whh[(size_t)rg1 * H2_DIM + 2 * k2 + 1]);
    }

    // GEMM ownership: thread -> rows (r0, r0+1) x batches (4ty .. 4ty+3)
    const int tx = tid & 15, ty = tid >> 4;
    const int r0 = 2 * tx;
    const int rg0 = (r0 >> 3) * H2_DIM + hseg * 8 + (r0 & 7);  // rg1 = rg0+1
    const int bp0 = 2 * ty, bp1 = 2 * ty + 1;

    // staging ownership: thread -> batch (tid&31), 32-k span (tid>>5)*32
    const int stg_b  = tid & 31;
    const int kbase0 = (tid >> 5) * 32;
    const int stg_bp = stg_b >> 1;
    const int stg_c  = stg_b & 1;

    // pointwise ownership: thread -> (b = tid>>3, hh = tid&7) and (b+16, hh)
    const int bq0 = tid >> 3, hh = tid & 7;
    const int hidx = hseg * 8 + hh;
    float c_0 = c0[dir * B_SZ * H2_DIM + (bbase + bq0) * H2_DIM + hidx];
    float c_1 = c0[dir * B_SZ * H2_DIM + (bbase + bq0 + 16) * H2_DIM + hidx];

    // G loads for step 0
    float2 gv[4];
    {
        const int s0 = dir ? (S_LEN - 1) : 0;
#pragma unroll
        for (int u = 0; u < 4; ++u)
            gv[u] = *(const float2*)&Gin[(size_t)(s0 * B_SZ + bbase + 4 * ty + u) * G4 + rg0];
    }

    __syncthreads();

    for (int it = 0; it < S_LEN; ++it) {
        const int s = dir ? (S_LEN - 1 - it) : it;
        const int p = it & 1;
        const float* hprev = &d_hstate[p][dir][0][0];
        float* hnext = &d_hstate[p ^ 1][dir][0][0];
        const float* hp = &hprev[(bbase + stg_b) * H2_DIM];

        // prefetch chunk 0 of hprev (32 consecutive k values for one batch)
        float4 pf[8];
#pragma unroll
        for (int u = 0; u < 8; ++u)
            pf[u] = __ldcg((const float4*)&hp[kbase0 + 4 * u]);

        ull a00 = 0ull, a01 = 0ull, a10 = 0ull, a11 = 0ull;
        // a00: row r0, batches (4ty,4ty+1); a10: row r0+1, same
        // a01: row r0, batches (4ty+2,4ty+3); a11: row r0+1, same

#pragma unroll 1
        for (int c = 0; c < 2; ++c) {
            // store prefetched chunk c into Hsv (k-pair interleaved)
#pragma unroll
            for (int u = 0; u < 8; ++u) {
                int kl = kbase0 + 4 * u;          // multiple of 4
                int k2l = kl >> 1;                // even, 0..62
                float* t0 = &Hsv[k2l][stg_bp].x;
                t0[stg_c] = pf[u].x; t0[2 + stg_c] = pf[u].y;
                float* t1 = &Hsv[k2l + 1][stg_bp].x;
                t1[stg_c] = pf[u].z; t1[2 + stg_c] = pf[u].w;
            }
            // prefetch chunk 1 (consumed after ~1300 cyc of chunk-0 compute)
            if (c == 0) {
#pragma unroll
                for (int u = 0; u < 8; ++u)
                    pf[u] = __ldcg((const float4*)&hp[128 + kbase0 + 4 * u]);
            }
            __syncthreads();

#pragma unroll 8
            for (int k2l = 0; k2l < 64; ++k2l) {
                float4 wq = Ws4[c * 64 + k2l][tx];
                ulonglong2 h0 = *(const ulonglong2*)&Hsv[k2l][bp0];
                ulonglong2 h1 = *(const ulonglong2*)&Hsv[k2l][bp1];
                ull w00 = pk2(wq.x, wq.x);   // k even, row r0
                ull w01 = pk2(wq.y, wq.y);   // k even, row r0+1
                ull w10 = pk2(wq.z, wq.z);   // k odd,  row r0
                ull w11 = pk2(wq.w, wq.w);   // k odd,  row r0+1
                fma2(a00, h0.x, w00); fma2(a10, h0.x, w01);
                fma2(a00, h0.y, w10); fma2(a10, h0.y, w11);
                fma2(a01, h1.x, w00); fma2(a11, h1.x, w01);
                fma2(a01, h1.y, w10); fma2(a11, h1.y, w11);
            }
            __syncthreads();
        }

        // write gates to exchange buffer (+ x-part from G); aliases Hsv,
        // safe: last compute sync above guarantees all Hsv reads complete.
        {
            float2 u00 = up2(a00), u10 = up2(a10), u01 = up2(a01), u11 = up2(a11);
            int b0 = 4 * ty;
            Gsm[b0 + 0][r0]     = u00.x + gv[0].x;
            Gsm[b0 + 0][r0 + 1] = u10.x + gv[0].y;
            Gsm[b0 + 1][r0]     = u00.y + gv[1].x;
            Gsm[b0 + 1][r0 + 1] = u10.y + gv[1].y;
            Gsm[b0 + 2][r0]     = u01.x + gv[2].x;
            Gsm[b0 + 2][r0 + 1] = u11.x + gv[2].y;
            Gsm[b0 + 3][r0]     = u01.y + gv[3].x;
            Gsm[b0 + 3][r0 + 1] = u11.y + gv[3].y;
        }
        __syncthreads();

        // pointwise: two (b,h) pairs per thread
        {
            float gi = Gsm[bq0][hh], gf = Gsm[bq0][8 + hh];
            float gg = Gsm[bq0][16 + hh], go = Gsm[bq0][24 + hh];
            float si = 1.f / (1.f + expf(-gi));
            float sf = 1.f / (1.f + expf(-gf));
            float so = 1.f / (1.f + expf(-go));
            c_0 = sf * c_0 + si * tanhf(gg);
            float h = so * tanhf(c_0);
            __stcg(&hnext[(bbase + bq0) * H2_DIM + hidx], h);
            d_Hout[s * B_SZ + bbase + bq0][dir * H2_DIM + hidx] = h;
        }
        {
            int b1 = bq0 + 16;
            float gi = Gsm[b1][hh], gf = Gsm[b1][8 + hh];
            float gg = Gsm[b1][16 + hh], go = Gsm[b1][24 + hh];
            float si = 1.f / (1.f + expf(-gi));
            float sf = 1.f / (1.f + expf(-gf));
            float so = 1.f / (1.f + expf(-go));
            c_1 = sf * c_1 + si * tanhf(gg);
            float h = so * tanhf(c_1);
            __stcg(&hnext[(bbase + b1) * H2_DIM + hidx], h);
            d_Hout[s * B_SZ + bbase + b1][dir * H2_DIM + hidx] = h;
        }

        if (it < S_LEN - 1) {
            // prefetch next step's G BEFORE the barrier (independent of h)
            const int sn = dir ? (S_LEN - 2 - it) : (it + 1);
            float2 gvn[4];
#pragma unroll
            for (int u = 0; u < 4; ++u)
                gvn[u] = *(const float2*)&Gin[(size_t)(sn * B_SZ + bbase + 4 * ty + u) * G4 + rg0];

            // group barrier: arrive on own sub-counter (8 RMWs each), poll 4
            __syncthreads();
            if (tid == 0) {
                bar_arrive(my_cnt);
                const unsigned int target = (unsigned int)(it + 1) * 8;
                while (bar_ld_acq(cbase) < target) { }
                while (bar_ld_acq(cbase + 32) < target) { }
                while (bar_ld_acq(cbase + 64) < target) { }
                while (bar_ld_acq(cbase + 96) < target) { }
            }
            __syncthreads();

#pragma unroll
            for (int u = 0; u < 4; ++u) gv[u] = gvn[u];
        }
    }
}

// ---------------- feats: (16384 x 512) @ (512 x 10) + b ---------------------
__global__ __launch_bounds__(256) void feats_kernel(
    const float* __restrict__ W_out, const float* __restrict__ b_out)
{
    const int warp = threadIdx.x >> 5;
    const int lane = threadIdx.x & 31;
    const int n = blockIdx.x * 8 + warp;
    const float4* h4 = (const float4*)&d_Hout[n][0];

    float acc[T_TAGS];
#pragma unroll
    for (int t = 0; t < T_TAGS; ++t) acc[t] = 0.f;

#pragma unroll
    for (int i = 0; i < 4; ++i) {
        int q = i * 32 + lane;               // float4 index (0..127)
        float4 hv = h4[q];
#pragma unroll
        for (int t = 0; t < T_TAGS; ++t) {
            float4 w = *(const float4*)&W_out[t * H_DIM + q * 4];
            acc[t] += hv.x * w.x + hv.y * w.y + hv.z * w.z + hv.w * w.w;
        }
    }
#pragma unroll
    for (int t = 0; t < T_TAGS; ++t) {
        float v = acc[t];
#pragma unroll
        for (int off = 16; off > 0; off >>= 1)
            v += __shfl_down_sync(0xffffffffu, v, off);
        if (lane == 0) d_feats[n][t] = v + b_out[t];
    }
}

// ---------------- Viterbi: one warp per batch --------------------------------
// All 2560 emission floats for the batch staged into smem up front (pipelined
// float4 copy) so the serial 256-step chain reads LDS, not L2.
// Also resets the lstm barrier counters (stream-ordered after lstm_kernel).
__global__ void viterbi_kernel(const float* __restrict__ trans, float* __restrict__ out) {
    const int b = blockIdx.x;
    const int lane = threadIdx.x;
    __shared__ float tr[T_TAGS][T_TAGS];
    __shared__ __align__(16) float fsm[S_LEN * T_TAGS];   // 10.24 KB
    __shared__ unsigned char bp[S_LEN][T_TAGS];

    if (b == 0 && lane < 16) d_cnt[lane][0] = 0u;

    for (int i = lane; i < T_TAGS * T_TAGS; i += 32)
        tr[i / T_TAGS][i % T_TAGS] = trans[i];

    // bulk-stage emissions: 2560 contiguous floats = 640 float4
    {
        const float4* src = (const float4*)&d_feats[b * S_LEN][0];
        float4* dst = (float4*)fsm;
        for (int i = lane; i < 640; i += 32)
            dst[i] = src[i];
    }
    __syncwarp();

    const int ln = lane < T_TAGS ? lane : 0;   // safe index for lanes >= 10
    float fv = (lane == START_TAG) ? 0.f : -10000.f;

    for (int s = 0; s < S_LEN; ++s) {
        float best = -3.4e38f;
        int arg = 0;
#pragma unroll
        for (int pv = 0; pv < T_TAGS; ++pv) {
            float fp = __shfl_sync(0xffffffffu, fv, pv);
            float v = fp + tr[ln][pv];
            if (v > best) { best = v; arg = pv; }   // strict > keeps FIRST max
        }
        if (lane < T_TAGS) bp[s][lane] = (unsigned char)arg;
        fv = best + fsm[s * T_TAGS + ln];
        __syncwarp();
    }

    float term = fv + tr[STOP_TAG][ln];
    __syncwarp();

    float bestv = -3.4e38f;
    int bestt = 0;
#pragma unroll
    for (int t = 0; t < T_TAGS; ++t) {
        float v = __shfl_sync(0xffffffffu, term, t);
        if (v > bestv) { bestv = v; bestt = t; }
    }

    if (lane == 0) {
        out[b] = bestv;                      // path_score (B,1)
        float* pathout = out + B_SZ + b * S_LEN;
        int cur = bestt;
        pathout[S_LEN - 1] = (float)cur;
        for (int s = S_LEN - 2; s >= 0; --s) {
            cur = bp[s + 1][cur];
            pathout[s] = (float)cur;
        }
    }
}

// ---------------- launch ------------------------------------------------------
extern "C" void kernel_launch(void* const* d_in, const int* in_sizes, int n_in,
                              void* d_out, int out_size) {
    const int*   sent  = (const int*)  d_in[0];
    const float* emb   = (const float*)d_in[1];
    const float* wih_f = (const float*)d_in[2];
    const float* whh_f = (const float*)d_in[3];
    const float* bih_f = (const float*)d_in[4];
    const float* bhh_f = (const float*)d_in[5];
    const float* wih_b = (const float*)d_in[6];
    const float* whh_b = (const float*)d_in[7];
    const float* bih_b = (const float*)d_in[8];
    const float* bhh_b = (const float*)d_in[9];
    const float* W_out = (const float*)d_in[10];
    const float* b_out = (const float*)d_in[11];

    // Resolve trailing-argument order at runtime (transitions = 100 elems).
    const float *trans, *h0, *c0;
    if (n_in >= 15 && in_sizes[12] == 100) {
        trans = (const float*)d_in[12];
        h0    = (const float*)d_in[13];
        c0    = (const float*)d_in[14];
    } else {
        h0    = (const float*)d_in[12];
        c0    = (const float*)d_in[13];
        trans = (const float*)d_in[14];
    }

    float* out = (float*)d_out;

    dim3 g(NTOK / 64, G4 / 64, 2);   // 256 x 16 x 2
    input_gemm_kernel<<<g, 256>>>(sent, emb, wih_f, bih_f, bhh_f,
                                  wih_b, bih_b, bhh_b, h0);
    // two no-op launches position lstm_kernel as the 4th launch, which is the
    // one the fixed ncu window captures — we need its profile.
    noop_kernel<<<1, 1>>>();
    noop_kernel<<<1, 1>>>();
    lstm_kernel<<<LSTM_BLOCKS, 128>>>(whh_f, whh_b, c0);
    feats_kernel<<<NTOK / 8, 256>>>(W_out, b_out);
    viterbi_kernel<<<B_SZ, 32>>>(trans, out);
    (void)out_size; (void)n_in;
}

// round 17
// speedup vs baseline: 1.7798x; 1.0402x over previous
#include <cuda_runtime.h>
#include <math.h>
#include <stdint.h>

// Problem constants
#define S_LEN   256
#define B_SZ    64
#define E_DIM   300
#define H2_DIM  256
#define H_DIM   512
#define T_TAGS  10
#define START_TAG 8
#define STOP_TAG  9
#define NTOK    (S_LEN * B_SZ)     // 16384
#define G4      (4 * H2_DIM)       // 1024

#define LSTM_BLOCKS 128

typedef unsigned long long ull;

// ---------- packed f32x2 helpers (exact fp32, 2x FMA-pipe throughput) ------
__device__ __forceinline__ ull pk2(float x, float y) {
    ull r;
    asm("mov.b64 %0, {%1, %2};" : "=l"(r) : "f"(x), "f"(y));
    return r;
}
__device__ __forceinline__ void fma2(ull& c, ull a, ull b) {
    asm("fma.rn.f32x2 %0, %1, %2, %0;" : "+l"(c) : "l"(a), "l"(b));
}
__device__ __forceinline__ float2 up2(ull v) {
    float2 r;
    asm("mov.b64 {%0, %1}, %2;" : "=f"(r.x), "=f"(r.y) : "l"(v));
    return r;
}

// ---------------- scratch (device globals; no allocation allowed) ----------
__device__ __align__(16) float d_G[2][NTOK][G4];        // gate preactivations (x part + biases)
__device__ __align__(16) float d_Hout[NTOK][H_DIM];     // concatenated hidden states (S*B, 512)
__device__ __align__(16) float d_feats[NTOK][T_TAGS];   // emission scores
// 4-deep rotation so blocks may skew by one step under the dataflow flags
// without write-after-read hazards: step it reads buf[it&3], writes buf[(it+1)&3].
__device__ __align__(16) float d_hstate[4][2][B_SZ][H2_DIM];
// 16 monotonic chunk-flag counters: group (dir x bh) x 4 h-octet chunks.
// Producer hseg arrives on counter[grp][hseg>>3]; counter reaches 8*(it+1)
// once all 8 producers of that chunk published step it's h. Zero-init .bss;
// reset by viterbi_kernel (stream-ordered after lstm) for graph replays.
__device__ __align__(256) unsigned int d_cnt[16][32];

// ---------- flag primitives (release-red arrive, acquire poll) -------------
__device__ __forceinline__ void bar_arrive(unsigned int* c) {
    asm volatile("red.release.gpu.global.add.u32 [%0], 1;" :: "l"(c) : "memory");
}
__device__ __forceinline__ unsigned int bar_ld_acq(const unsigned int* c) {
    unsigned int v;
    asm volatile("ld.acquire.gpu.global.u32 %0, [%1];" : "=r"(v) : "l"(c) : "memory");
    return v;
}

// ---------------- no-op kernels (position lstm as the 4th launch for ncu) --
__global__ void noop_kernel() {}

// ---------------- input GEMM: G = gather(emb, tok) @ wih^T + bih + bhh -----
// M=16384 (64-tile), N=1024 (64-tile), K=300 (12-tile, 25 iters exact)
// Block (0,0,0) additionally seeds d_hstate[0] from h0.
__global__ __launch_bounds__(256) void input_gemm_kernel(
    const int*   __restrict__ sent,
    const float* __restrict__ emb,
    const float* __restrict__ wih_f, const float* __restrict__ bih_f, const float* __restrict__ bhh_f,
    const float* __restrict__ wih_b, const float* __restrict__ bih_b, const float* __restrict__ bhh_b,
    const float* __restrict__ h0)
{
    const int dir = blockIdx.z;
    const float* wih = dir ? wih_b : wih_f;
    const float* bih = dir ? bih_b : bih_f;
    const float* bhh = dir ? bhh_b : bhh_f;
    float* Gout = &d_G[dir][0][0];

    __shared__ __align__(16) float As[12][64];
    __shared__ __align__(16) float Bs[12][64];
    __shared__ int toks[64];

    const int tid = threadIdx.x;
    const int n0 = blockIdx.x * 64;
    const int j0 = blockIdx.y * 64;

    if (blockIdx.x == 0 && blockIdx.y == 0 && blockIdx.z == 0) {
        float* dst = &d_hstate[0][0][0][0];
        for (int i = tid; i < 2 * B_SZ * H2_DIM; i += 256)
            dst[i] = h0[i];
    }

    if (tid < 64) toks[tid] = sent[n0 + tid];
    __syncthreads();

    const int tx = tid & 15;        // j quad
    const int ty = tid >> 4;        // n quad
    ull acc[4][2];
#pragma unroll
    for (int i = 0; i < 4; ++i) { acc[i][0] = 0ull; acc[i][1] = 0ull; }

    for (int k0 = 0; k0 < E_DIM; k0 += 12) {
#pragma unroll
        for (int i = 0; i < 3; ++i) {
            int idx = i * 256 + tid;            // 0..767 = 64 rows * 12 k
            int nn = idx / 12, kk = idx % 12;
            As[kk][nn] = emb[(size_t)toks[nn] * E_DIM + k0 + kk];
            Bs[kk][nn] = wih[(size_t)(j0 + nn) * E_DIM + k0 + kk];
        }
        __syncthreads();
#pragma unroll
        for (int kk = 0; kk < 12; ++kk) {
            float4 a = *(const float4*)&As[kk][ty * 4];
            ulonglong2 bv = *(const ulonglong2*)&Bs[kk][tx * 4];
            ull pa0 = pk2(a.x, a.x);
            ull pa1 = pk2(a.y, a.y);
            ull pa2 = pk2(a.z, a.z);
            ull pa3 = pk2(a.w, a.w);
            fma2(acc[0][0], pa0, bv.x); fma2(acc[0][1], pa0, bv.y);
            fma2(acc[1][0], pa1, bv.x); fma2(acc[1][1], pa1, bv.y);
            fma2(acc[2][0], pa2, bv.x); fma2(acc[2][1], pa2, bv.y);
            fma2(acc[3][0], pa3, bv.x); fma2(acc[3][1], pa3, bv.y);
        }
        __syncthreads();
    }

    float4 bi = *(const float4*)&bih[j0 + tx * 4];
    float4 bh = *(const float4*)&bhh[j0 + tx * 4];
    float bs0 = bi.x + bh.x, bs1 = bi.y + bh.y, bs2 = bi.z + bh.z, bs3 = bi.w + bh.w;
#pragma unroll
    for (int ii = 0; ii < 4; ++ii) {
        int n = n0 + ty * 4 + ii;
        float2 lo = up2(acc[ii][0]);
        float2 hi = up2(acc[ii][1]);
        float4 o = make_float4(lo.x + bs0, lo.y + bs1, hi.x + bs2, hi.y + bs3);
        *(float4*)&Gout[(size_t)n * G4 + j0 + tx * 4] = o;
    }
}

// ---------------- persistent bidirectional LSTM (dataflow flags) -----------
// R10 structure verbatim (128 blocks x 128 threads; dir x batch-half x hseg
// of 8 h-units; 4 chunks of 64 k) with the monolithic barrier replaced by
// per-chunk producer flags: consumers poll counter[c] just before staging
// chunk c, so waiting overlaps compute of earlier chunks and only the 8
// producers of chunk 0 gate the step start.
__global__ __launch_bounds__(128, 1) void lstm_kernel(
    const float* __restrict__ whh_f,
    const float* __restrict__ whh_b,
    const float* __restrict__ c0)
{
    const int dir   = blockIdx.x >> 6;
    const int slice = blockIdx.x & 63;
    const int bh    = slice >> 5;     // 0/1 batch half
    const int hseg  = slice & 31;     // hidden segment (8 units -> 32 gate rows)
    const int bbase = bh * 32;
    const int tid   = threadIdx.x;
    const int grp   = dir * 2 + bh;   // flag group (0..3)
    unsigned int* my_cnt = &d_cnt[grp * 4 + (hseg >> 3)][0];
    const unsigned int* cbase = &d_cnt[grp * 4][0];

    // Ws4[k2][rp] = (w[2k2][2rp], w[2k2][2rp+1], w[2k2+1][2rp], w[2k2+1][2rp+1])
    __shared__ __align__(16) float4 Ws4[128][16];   // 32 KB (whole Whh slice)
    // Hsv[k2][bp] = (h[2k2][2bp], h[2k2][2bp+1], h[2k2+1][2bp], h[2k2+1][2bp+1])
    __shared__ __align__(16) float4 Hsv[32][16];    // 8 KB (one 64-k chunk)
    __shared__ float Gsm[32][33];                   // gate exchange [b_local][r]

    const float* whh = dir ? whh_b : whh_f;
    const float* Gin = &d_G[dir][0][0];

    // Build Ws4 once (2048 float4 entries, 16 per thread)
    for (int i = tid; i < 128 * 16; i += 128) {
        int k2 = i >> 4, rp = i & 15;
        int r0 = 2 * rp, r1 = r0 + 1;
        int rg0 = (r0 >> 3) * H2_DIM + hseg * 8 + (r0 & 7);
        int rg1 = (r1 >> 3) * H2_DIM + hseg * 8 + (r1 & 7);
        Ws4[k2][rp] = make_float4(whh[(size_t)rg0 * H2_DIM + 2 * k2],
                                  whh[(size_t)rg1 * H2_DIM + 2 * k2],
                                  whh[(size_t)rg0 * H2_DIM + 2 * k2 + 1],
                                  whh[(size_t)rg1 * H2_DIM + 2 * k2 + 1]);
    }

    // GEMM ownership: thread -> rows (r0, r0+1) x batches (4ty .. 4ty+3)
    const int tx = tid & 15, ty = tid >> 4;
    const int r0 = 2 * tx;
    const int rg0 = (r0 >> 3) * H2_DIM + hseg * 8 + (r0 & 7);  // rg1 = rg0+1
    const int bp0 = 2 * ty, bp1 = 2 * ty + 1;

    // staging ownership: thread -> batch (tid&31), k quarter (tid>>5)
    const int stg_b  = tid & 31;
    const int kbase0 = (tid >> 5) * 16;
    const int stg_bp = stg_b >> 1;
    const int stg_c  = stg_b & 1;

    // pointwise ownership: thread -> (b = tid>>3, hh = tid&7) and (b+16, hh)
    const int bq0 = tid >> 3, hh = tid & 7;
    const int hidx = hseg * 8 + hh;
    float c_0 = c0[dir * B_SZ * H2_DIM + (bbase + bq0) * H2_DIM + hidx];
    float c_1 = c0[dir * B_SZ * H2_DIM + (bbase + bq0 + 16) * H2_DIM + hidx];

    // G loads for step 0
    float2 gv[4];
    {
        const int s0 = dir ? (S_LEN - 1) : 0;
#pragma unroll
        for (int u = 0; u < 4; ++u)
            gv[u] = *(const float2*)&Gin[(size_t)(s0 * B_SZ + bbase + 4 * ty + u) * G4 + rg0];
    }

    __syncthreads();

    for (int it = 0; it < S_LEN; ++it) {
        const int s = dir ? (S_LEN - 1 - it) : it;
        const float* hprev = &d_hstate[it & 3][dir][0][0];
        float* hnext = &d_hstate[(it + 1) & 3][dir][0][0];
        const float* hp = &hprev[(bbase + stg_b) * H2_DIM];
        const unsigned int tgt = (unsigned int)it * 8u;

        // chunk-0 flag: probe early, then confirm (orders subsequent h LDGs)
        if (it > 0) {
            unsigned int v = bar_ld_acq(cbase);
            while (v < tgt) v = bar_ld_acq(cbase);
        }

        // prefetch chunk 0 of hprev
        float4 pf[4];
#pragma unroll
        for (int u = 0; u < 4; ++u)
            pf[u] = __ldcg((const float4*)&hp[kbase0 + 4 * u]);

        ull a00 = 0ull, a01 = 0ull, a10 = 0ull, a11 = 0ull;

#pragma unroll 1
        for (int c = 0; c < 4; ++c) {
            // probe next chunk's flag first (acquire issued; overlaps the STS)
            unsigned int vprobe = 0xFFFFFFFFu;
            if (c < 3 && it > 0) vprobe = bar_ld_acq(cbase + 32 * (c + 1));

            // store prefetched chunk c into Hsv
#pragma unroll
            for (int u = 0; u < 4; ++u) {
                int kl = kbase0 + 4 * u;          // multiple of 4
                int k2l = kl >> 1;                // even
                float* t0 = &Hsv[k2l][stg_bp].x;
                t0[stg_c] = pf[u].x; t0[2 + stg_c] = pf[u].y;
                float* t1 = &Hsv[k2l + 1][stg_bp].x;
                t1[stg_c] = pf[u].z; t1[2 + stg_c] = pf[u].w;
            }
            // confirm flag, then prefetch chunk c+1 (hidden behind compute c)
            if (c < 3) {
                if (it > 0) {
                    unsigned int v = vprobe;
                    while (v < tgt) v = bar_ld_acq(cbase + 32 * (c + 1));
                }
#pragma unroll
                for (int u = 0; u < 4; ++u)
                    pf[u] = __ldcg((const float4*)&hp[(c + 1) * 64 + kbase0 + 4 * u]);
            }
            __syncthreads();

#pragma unroll 8
            for (int k2l = 0; k2l < 32; ++k2l) {
                float4 wq = Ws4[c * 32 + k2l][tx];
                ulonglong2 h0 = *(const ulonglong2*)&Hsv[k2l][bp0];
                ulonglong2 h1 = *(const ulonglong2*)&Hsv[k2l][bp1];
                ull w00 = pk2(wq.x, wq.x);   // k even, row r0
                ull w01 = pk2(wq.y, wq.y);   // k even, row r0+1
                ull w10 = pk2(wq.z, wq.z);   // k odd,  row r0
                ull w11 = pk2(wq.w, wq.w);   // k odd,  row r0+1
                fma2(a00, h0.x, w00); fma2(a10, h0.x, w01);
                fma2(a00, h0.y, w10); fma2(a10, h0.y, w11);
                fma2(a01, h1.x, w00); fma2(a11, h1.x, w01);
                fma2(a01, h1.y, w10); fma2(a11, h1.y, w11);
            }
            __syncthreads();
        }

        // write gates to exchange buffer (+ x-part from G)
        {
            float2 u00 = up2(a00), u10 = up2(a10), u01 = up2(a01), u11 = up2(a11);
            int b0 = 4 * ty;
            Gsm[b0 + 0][r0]     = u00.x + gv[0].x;
            Gsm[b0 + 0][r0 + 1] = u10.x + gv[0].y;
            Gsm[b0 + 1][r0]     = u00.y + gv[1].x;
            Gsm[b0 + 1][r0 + 1] = u10.y + gv[1].y;
            Gsm[b0 + 2][r0]     = u01.x + gv[2].x;
            Gsm[b0 + 2][r0 + 1] = u11.x + gv[2].y;
            Gsm[b0 + 3][r0]     = u01.y + gv[3].x;
            Gsm[b0 + 3][r0 + 1] = u11.y + gv[3].y;
        }
        __syncthreads();

        // pointwise: two (b,h) pairs per thread -> publish h, THEN arrive
        float h_0, h_1;
        {
            float gi = Gsm[bq0][hh], gf = Gsm[bq0][8 + hh];
            float gg = Gsm[bq0][16 + hh], go = Gsm[bq0][24 + hh];
            float si = 1.f / (1.f + expf(-gi));
            float sf = 1.f / (1.f + expf(-gf));
            float so = 1.f / (1.f + expf(-go));
            c_0 = sf * c_0 + si * tanhf(gg);
            h_0 = so * tanhf(c_0);
            __stcg(&hnext[(bbase + bq0) * H2_DIM + hidx], h_0);
        }
        {
            int b1 = bq0 + 16;
            float gi = Gsm[b1][hh], gf = Gsm[b1][8 + hh];
            float gg = Gsm[b1][16 + hh], go = Gsm[b1][24 + hh];
            float si = 1.f / (1.f + expf(-gi));
            float sf = 1.f / (1.f + expf(-gf));
            float so = 1.f / (1.f + expf(-go));
            c_1 = sf * c_1 + si * tanhf(gg);
            h_1 = so * tanhf(c_1);
            __stcg(&hnext[(bbase + b1) * H2_DIM + hidx], h_1);
        }
        __syncthreads();                 // all h stores of this block issued
        if (tid == 0) bar_arrive(my_cnt);  // publish: counter -> 8*(it+1)

        // off the critical path: Hout stores + next step's G prefetch
        d_Hout[s * B_SZ + bbase + bq0][dir * H2_DIM + hidx] = h_0;
        d_Hout[s * B_SZ + bbase + bq0 + 16][dir * H2_DIM + hidx] = h_1;

        if (it < S_LEN - 1) {
            const int sn = dir ? (S_LEN - 2 - it) : (it + 1);
#pragma unroll
            for (int u = 0; u < 4; ++u)
                gv[u] = *(const float2*)&Gin[(size_t)(sn * B_SZ + bbase + 4 * ty + u) * G4 + rg0];
        }
    }
}

// ---------------- feats: (16384 x 512) @ (512 x 10) + b ---------------------
__global__ __launch_bounds__(256) void feats_kernel(
    const float* __restrict__ W_out, const float* __restrict__ b_out)
{
    const int warp = threadIdx.x >> 5;
    const int lane = threadIdx.x & 31;
    const int n = blockIdx.x * 8 + warp;
    const float4* h4 = (const float4*)&d_Hout[n][0];

    float acc[T_TAGS];
#pragma unroll
    for (int t = 0; t < T_TAGS; ++t) acc[t] = 0.f;

#pragma unroll
    for (int i = 0; i < 4; ++i) {
        int q = i * 32 + lane;               // float4 index (0..127)
        float4 hv = h4[q];
#pragma unroll
        for (int t = 0; t < T_TAGS; ++t) {
            float4 w = *(const float4*)&W_out[t * H_DIM + q * 4];
            acc[t] += hv.x * w.x + hv.y * w.y + hv.z * w.z + hv.w * w.w;
        }
    }
#pragma unroll
    for (int t = 0; t < T_TAGS; ++t) {
        float v = acc[t];
#pragma unroll
        for (int off = 16; off > 0; off >>= 1)
            v += __shfl_down_sync(0xffffffffu, v, off);
        if (lane == 0) d_feats[n][t] = v + b_out[t];
    }
}

// ---------------- Viterbi: one warp per batch --------------------------------
// Emissions bulk-staged into smem; resets the lstm chunk-flag counters.
__global__ void viterbi_kernel(const float* __restrict__ trans, float* __restrict__ out) {
    const int b = blockIdx.x;
    const int lane = threadIdx.x;
    __shared__ float tr[T_TAGS][T_TAGS];
    __shared__ __align__(16) float fsm[S_LEN * T_TAGS];   // 10.24 KB
    __shared__ unsigned char bp[S_LEN][T_TAGS];

    if (b == 0 && lane < 16) d_cnt[lane][0] = 0u;

    for (int i = lane; i < T_TAGS * T_TAGS; i += 32)
        tr[i / T_TAGS][i % T_TAGS] = trans[i];

    // bulk-stage emissions: 2560 contiguous floats = 640 float4
    {
        const float4* src = (const float4*)&d_feats[b * S_LEN][0];
        float4* dst = (float4*)fsm;
        for (int i = lane; i < 640; i += 32)
            dst[i] = src[i];
    }
    __syncwarp();

    const int ln = lane < T_TAGS ? lane : 0;   // safe index for lanes >= 10
    float fv = (lane == START_TAG) ? 0.f : -10000.f;

    for (int s = 0; s < S_LEN; ++s) {
        float best = -3.4e38f;
        int arg = 0;
#pragma unroll
        for (int pv = 0; pv < T_TAGS; ++pv) {
            float fp = __shfl_sync(0xffffffffu, fv, pv);
            float v = fp + tr[ln][pv];
            if (v > best) { best = v; arg = pv; }   // strict > keeps FIRST max
        }
        if (lane < T_TAGS) bp[s][lane] = (unsigned char)arg;
        fv = best + fsm[s * T_TAGS + ln];
        __syncwarp();
    }

    float term = fv + tr[STOP_TAG][ln];
    __syncwarp();

    float bestv = -3.4e38f;
    int bestt = 0;
#pragma unroll
    for (int t = 0; t < T_TAGS; ++t) {
        float v = __shfl_sync(0xffffffffu, term, t);
        if (v > bestv) { bestv = v; bestt = t; }
    }

    if (lane == 0) {
        out[b] = bestv;                      // path_score (B,1)
        float* pathout = out + B_SZ + b * S_LEN;
        int cur = bestt;
        pathout[S_LEN - 1] = (float)cur;
        for (int s = S_LEN - 2; s >= 0; --s) {
            cur = bp[s + 1][cur];
            pathout[s] = (float)cur;
        }
    }
}

// ---------------- launch ------------------------------------------------------
extern "C" void kernel_launch(void* const* d_in, const int* in_sizes, int n_in,
                              void* d_out, int out_size) {
    const int*   sent  = (const int*)  d_in[0];
    const float* emb   = (const float*)d_in[1];
    const float* wih_f = (const float*)d_in[2];
    const float* whh_f = (const float*)d_in[3];
    const float* bih_f = (const float*)d_in[4];
    const float* bhh_f = (const float*)d_in[5];
    const float* wih_b = (const float*)d_in[6];
    const float* whh_b = (const float*)d_in[7];
    const float* bih_b = (const float*)d_in[8];
    const float* bhh_b = (const float*)d_in[9];
    const float* W_out = (const float*)d_in[10];
    const float* b_out = (const float*)d_in[11];

    // Resolve trailing-argument order at runtime (transitions = 100 elems).
    const float *trans, *h0, *c0;
    if (n_in >= 15 && in_sizes[12] == 100) {
        trans = (const float*)d_in[12];
        h0    = (const float*)d_in[13];
        c0    = (const float*)d_in[14];
    } else {
        h0    = (const float*)d_in[12];
        c0    = (const float*)d_in[13];
        trans = (const float*)d_in[14];
    }

    float* out = (float*)d_out;

    dim3 g(NTOK / 64, G4 / 64, 2);   // 256 x 16 x 2
    input_gemm_kernel<<<g, 256>>>(sent, emb, wih_f, bih_f, bhh_f,
                                  wih_b, bih_b, bhh_b, h0);
    // two no-op launches keep lstm_kernel as the 4th launch for the ncu window
    noop_kernel<<<1, 1>>>();
    noop_kernel<<<1, 1>>>();
    lstm_kernel<<<LSTM_BLOCKS, 128>>>(whh_f, whh_b, c0);
    feats_kernel<<<NTOK / 8, 256>>>(W_out, b_out);
    viterbi_kernel<<<B_SZ, 32>>>(trans, out);
    (void)out_size; (void)n_in;
}